// round 4
// baseline (speedup 1.0000x reference)
#include <cuda_runtime.h>
#include <math.h>
#include <stdint.h>

#define Bn 16
#define NC 80
#define Hn 128
#define Wn 128
#define MAXO 100
#define HWc (Hn*Wn)
#define NBLK (Bn*32)   // 512 blocks: 32 row-groups (4 rows each) per batch

__device__ float4 g_partA[NBLK];   // neg, pos, giou, wsum
__device__ int    g_partN[NBLK];   // npos

// ---------------------------------------------------------------------------
// Fused kernel: inline per-batch prep + row-filtered scan + focal + GIoU
// grid = 512, block = 128 (4 warps; warp r owns row y0+r; lane owns 4 pixels)
// ---------------------------------------------------------------------------
__global__ void __launch_bounds__(128) main_kernel(const float* __restrict__ hm,
                                                   const float* __restrict__ wh,
                                                   const float* __restrict__ ann) {
    const int b    = blockIdx.x >> 5;
    const int rg   = blockIdx.x & 31;
    const int y0   = rg << 2;
    const int tid  = threadIdx.x;
    const int r    = tid >> 5;
    const int lane = tid & 31;
    const int y    = y0 + r;
    const int x0   = lane << 2;

    // ---- shared: prep scratch + sorted object table + per-row filtered lists
    __shared__ float s_ann[MAXO * 5];
    __shared__ float s_key[MAXO];
    __shared__ int   s_ord[MAXO];
    __shared__ float o_cx[MAXO], o_cy[MAXO], o_wr[MAXO], o_hr[MAXO];
    __shared__ float o_ix2[MAXO], o_iy2[MAXO], o_invg[MAXO];
    __shared__ float o_x1[MAXO], o_y1[MAXO], o_x2[MAXO], o_y2[MAXO];
    __shared__ int   o_cls[MAXO], o_valid[MAXO];
    __shared__ float fcx[4][MAXO], fwr[4][MAXO], fi2[4][MAXO], fgy[4][MAXO];
    __shared__ float fvg[4][MAXO], fb0[4][MAXO], fb1[4][MAXO], fb2[4][MAXO], fb3[4][MAXO];
    __shared__ int   fcl[4][MAXO];
    __shared__ int   f_cnt[4];

    // ================= inline prep (per-batch, recomputed per block) ========
    for (int i = tid; i < MAXO * 5; i += 128) s_ann[i] = ann[(size_t)b * MAXO * 5 + i];
    __syncthreads();

    if (tid < MAXO) {
        float cls  = s_ann[tid * 5 + 4];
        float area = (s_ann[tid * 5 + 3] - s_ann[tid * 5 + 1] + 1.0f)
                   * (s_ann[tid * 5 + 2] - s_ann[tid * 5 + 0] + 1.0f);
        s_key[tid] = (cls >= 0.0f) ? area : -3.4e38f;
    }
    __syncthreads();

    if (tid < MAXO) {   // stable rank sort, descending area
        float ki = s_key[tid];
        int rk = 0;
        #pragma unroll 4
        for (int j = 0; j < MAXO; j++) {
            float kj = s_key[j];
            rk += (kj > ki || (kj == ki && j < tid)) ? 1 : 0;
        }
        s_ord[rk] = tid;
    }
    __syncthreads();

    if (tid < MAXO) {
        int i = s_ord[tid];
        float x1 = s_ann[i*5+0], y1 = s_ann[i*5+1];
        float x2 = s_ann[i*5+2], y2 = s_ann[i*5+3], cls = s_ann[i*5+4];
        int valid = (cls >= 0.0f) ? 1 : 0;

        float cx = truncf((x1 + x2) * 0.5f / 4.0f);
        float cy = truncf((y1 + y2) * 0.5f / 4.0f);
        float fx1 = fminf(fmaxf(x1 * 0.25f, 0.0f), (float)(Wn - 1));
        float fx2 = fminf(fmaxf(x2 * 0.25f, 0.0f), (float)(Wn - 1));
        float fy1 = fminf(fmaxf(y1 * 0.25f, 0.0f), (float)(Hn - 1));
        float fy2 = fminf(fmaxf(y2 * 0.25f, 0.0f), (float)(Hn - 1));
        int hr = (int)((fy2 - fy1) * 0.5f * 0.54f);
        int wr = (int)((fx2 - fx1) * 0.5f * 0.54f);
        float sx = (float)(2 * wr + 1) / 6.0f;
        float sy = (float)(2 * hr + 1) / 6.0f;
        float ix2 = 1.0f / (2.0f * sx * sx);
        float iy2 = 1.0f / (2.0f * sy * sy);

        // analytic gsum via separable clipped-window sums
        int icx = (int)cx, icy = (int)cy;
        float sumx = 0.0f;
        int xa = max(0, icx - wr), xb = min(Wn - 1, icx + wr);
        for (int xx = xa; xx <= xb; xx++) {
            float dx = (float)xx - cx;
            sumx += __expf(-(dx * dx) * ix2);
        }
        float sumy = 0.0f;
        int ya = max(0, icy - hr), yb = min(Hn - 1, icy + hr);
        for (int yy = ya; yy <= yb; yy++) {
            float dy = (float)yy - cy;
            sumy += __expf(-(dy * dy) * iy2);
        }
        float gs = fmaxf(sumx * sumy, 1e-12f);

        int ic = (int)cls;
        ic = (ic < 0) ? 0 : ((ic > NC - 1) ? NC - 1 : ic);

        o_cx[tid] = cx;  o_cy[tid] = cy;
        o_wr[tid] = (float)wr;  o_hr[tid] = (float)hr;
        o_ix2[tid] = ix2;  o_iy2[tid] = iy2;
        o_invg[tid] = valid ? (1.0f / gs) : 0.0f;
        o_x1[tid] = x1; o_y1[tid] = y1; o_x2[tid] = x2; o_y2[tid] = y2;
        o_cls[tid] = ic; o_valid[tid] = valid;
    }
    __syncthreads();

    // ============ per-row filtered list (warp r -> row y0+r), order kept =====
    const float fyf = (float)y;
    {
        int cnt = 0;
        for (int base = 0; base < 128; base += 32) {
            int idx = base + lane;
            bool p = false;
            float dy = 0.0f;
            if (idx < MAXO && o_valid[idx]) {
                dy = fyf - o_cy[idx];
                p = fabsf(dy) <= o_hr[idx];
            }
            unsigned m = __ballot_sync(0xffffffffu, p);
            if (p) {
                int pos = cnt + __popc(m & ((1u << lane) - 1u));
                fcx[r][pos] = o_cx[idx];
                fwr[r][pos] = o_wr[idx];
                fi2[r][pos] = o_ix2[idx];
                fgy[r][pos] = __expf(-(dy * dy) * o_iy2[idx]);
                fvg[r][pos] = o_invg[idx];
                fb0[r][pos] = o_x1[idx]; fb1[r][pos] = o_y1[idx];
                fb2[r][pos] = o_x2[idx]; fb3[r][pos] = o_y2[idx];
                fcl[r][pos] = o_cls[idx];
            }
            cnt += __popc(m);
        }
        if (lane == 0) f_cnt[r] = cnt;
        __syncwarp();
    }
    const int fcnt = f_cnt[r];

    float accNeg = 0.0f, accPos = 0.0f, accG = 0.0f, accWs = 0.0f;
    int npos = 0;

    // ============ sparse part: covering scan + corrections + GIoU ===========
    #pragma unroll
    for (int p = 0; p < 4; p++) {
        const int   x  = x0 + p;
        const float fx = (float)x;
        int owner = -1;
        float gOwn = 0.0f;
        for (int i = 0; i < fcnt; i++) {
            float dx = fx - fcx[r][i];
            if (fabsf(dx) <= fwr[r][i]) {
                float gi = fgy[r][i] * __expf(-(dx * dx) * fi2[r][i]);
                owner = i; gOwn = gi;
                // per-class max dedupe via rescan (counts are tiny)
                bool isMax = true;
                int ci = fcl[r][i];
                for (int j = 0; j < fcnt; j++) {
                    if (j == i || fcl[r][j] != ci) continue;
                    float dxj = fx - fcx[r][j];
                    if (fabsf(dxj) <= fwr[r][j]) {
                        float gj = fgy[r][j] * __expf(-(dxj * dxj) * fi2[r][j]);
                        if (gj > gi || (gj == gi && j < i)) { isMax = false; break; }
                    }
                }
                if (isMax) {
                    float logit = hm[((size_t)b * NC + ci) * HWc + (size_t)y * Wn + x];
                    float e   = __expf(logit);
                    float u   = 1.0f + e;
                    float inv = __fdividef(1.0f, u);   // = 1 - sigmoid
                    float s   = e * inv;
                    float L   = __logf(u);             // = -log(1 - sigmoid)
                    float base = L * s * s;
                    if (gi == 1.0f) {
                        accPos += (L - logit) * inv * inv;   // -log(s)*(1-s)^2
                        accNeg -= base;
                        npos++;
                    } else {
                        float nt  = 1.0f - gi;
                        float nt2 = nt * nt;
                        accNeg += base * (nt2 * nt2 - 1.0f);
                    }
                }
            }
        }
        if (owner >= 0) {
            float w = gOwn * fvg[r][owner];
            size_t wb = (size_t)b * 4 * HWc + (size_t)y * Wn + x;
            float wh0 = wh[wb];
            float wh1 = wh[wb + HWc];
            float wh2 = wh[wb + 2 * (size_t)HWc];
            float wh3 = wh[wb + 3 * (size_t)HWc];
            float bx = fx * 4.0f, by = fyf * 4.0f;
            float p0 = bx - wh0, p1 = by - wh1, p2 = bx + wh2, p3 = by + wh3;
            float t0 = fb0[r][owner], t1 = fb1[r][owner];
            float t2 = fb2[r][owner], t3 = fb3[r][owner];
            float ltx = fmaxf(p0, t0), lty = fmaxf(p1, t1);
            float rbx = fminf(p2, t2), rby = fminf(p3, t3);
            float iw = fmaxf(rbx - ltx + 1.0f, 0.0f);
            float ih = fmaxf(rby - lty + 1.0f, 0.0f);
            float ov = iw * ih;
            float ap = (p2 - p0 + 1.0f) * (p3 - p1 + 1.0f);
            float ag = (t2 - t0 + 1.0f) * (t3 - t1 + 1.0f);
            float u  = ap + ag - ov;
            float iou = ov / u;
            float e1x = fminf(p0, t0), e1y = fminf(p1, t1);
            float e2x = fmaxf(p2, t2), e2y = fmaxf(p3, t3);
            float ew = fmaxf(e2x - e1x + 1.0f, 0.0f);
            float eh = fmaxf(e2y - e1y + 1.0f, 0.0f);
            float ea = ew * eh;
            float giou = iou - (ea - u) / ea;
            accG  += (1.0f - giou) * w;
            accWs += w;
        }
    }

    // ============ dense part: focal base (tgt = 0) over all classes =========
    {
        const float* hp = hm + ((size_t)b * NC) * HWc + (size_t)y * Wn + x0;
        float a0 = 0.0f, a1 = 0.0f;
        #pragma unroll 4
        for (int c = 0; c < NC; c++) {
            float4 v = *reinterpret_cast<const float4*>(hp + (size_t)c * HWc);
            {
                float e = __expf(v.x); float u = 1.0f + e;
                float s = e * __fdividef(1.0f, u);
                a0 += __logf(u) * s * s;
            }
            {
                float e = __expf(v.y); float u = 1.0f + e;
                float s = e * __fdividef(1.0f, u);
                a1 += __logf(u) * s * s;
            }
            {
                float e = __expf(v.z); float u = 1.0f + e;
                float s = e * __fdividef(1.0f, u);
                a0 += __logf(u) * s * s;
            }
            {
                float e = __expf(v.w); float u = 1.0f + e;
                float s = e * __fdividef(1.0f, u);
                a1 += __logf(u) * s * s;
            }
        }
        accNeg += a0 + a1;
    }

    // ============ block reduction -> per-block partial =======================
    #pragma unroll
    for (int off = 16; off > 0; off >>= 1) {
        accNeg += __shfl_down_sync(0xffffffffu, accNeg, off);
        accPos += __shfl_down_sync(0xffffffffu, accPos, off);
        accG   += __shfl_down_sync(0xffffffffu, accG,   off);
        accWs  += __shfl_down_sync(0xffffffffu, accWs,  off);
        npos   += __shfl_down_sync(0xffffffffu, npos,   off);
    }
    __shared__ float rNeg[4], rPos[4], rG[4], rW[4];
    __shared__ int   rN[4];
    if (lane == 0) { rNeg[r] = accNeg; rPos[r] = accPos; rG[r] = accG; rW[r] = accWs; rN[r] = npos; }
    __syncthreads();
    if (tid == 0) {
        float sn = 0.f, sp = 0.f, sg = 0.f, sw = 0.f; int np = 0;
        #pragma unroll
        for (int i = 0; i < 4; i++) { sn += rNeg[i]; sp += rPos[i]; sg += rG[i]; sw += rW[i]; np += rN[i]; }
        g_partA[blockIdx.x] = make_float4(sn, sp, sg, sw);
        g_partN[blockIdx.x] = np;
    }
}

// ---------------------------------------------------------------------------
// Finalize: reduce 512 partials (double), write 2 outputs
// ---------------------------------------------------------------------------
__global__ void __launch_bounds__(512) fin_kernel(float* out, int out_size) {
    int t = threadIdx.x;
    float4 v = g_partA[t];
    double n = v.x, p = v.y, g = v.z, w = v.w;
    int np = g_partN[t];

    #pragma unroll
    for (int off = 16; off > 0; off >>= 1) {
        n  += __shfl_down_sync(0xffffffffu, n,  off);
        p  += __shfl_down_sync(0xffffffffu, p,  off);
        g  += __shfl_down_sync(0xffffffffu, g,  off);
        w  += __shfl_down_sync(0xffffffffu, w,  off);
        np += __shfl_down_sync(0xffffffffu, np, off);
    }
    __shared__ double sn[16], sp[16], sg[16], sw[16];
    __shared__ int    sN[16];
    int wid = t >> 5, lane = t & 31;
    if (lane == 0) { sn[wid] = n; sp[wid] = p; sg[wid] = g; sw[wid] = w; sN[wid] = np; }
    __syncthreads();
    if (t == 0) {
        double N = 0, P = 0, G = 0, W = 0; int NP = 0;
        #pragma unroll
        for (int i = 0; i < 16; i++) { N += sn[i]; P += sp[i]; G += sg[i]; W += sw[i]; NP += sN[i]; }
        double hm_loss = (NP > 0) ? ((P + N) / (double)NP) : N;   // HM_W = 1
        double wh_loss = G / (W + 1e-4) * 0.1;                    // WH_W = 0.1
        if (out_size >= 1) out[0] = (float)hm_loss;
        if (out_size >= 2) out[1] = (float)wh_loss;
    }
}

// ---------------------------------------------------------------------------
extern "C" void kernel_launch(void* const* d_in, const int* in_sizes, int n_in,
                              void* d_out, int out_size) {
    const float* hm  = (const float*)d_in[0];   // (16, 80, 128, 128)
    const float* wh  = (const float*)d_in[1];   // (16, 4, 128, 128)
    const float* ann = (const float*)d_in[2];   // (16, 100, 5)
    float* out = (float*)d_out;

    main_kernel<<<NBLK, 128>>>(hm, wh, ann);
    fin_kernel<<<1, 512>>>(out, out_size);
}

// round 5
// speedup vs baseline: 1.6020x; 1.6020x over previous
#include <cuda_runtime.h>
#include <math.h>
#include <stdint.h>

#define Bn 16
#define NC 80
#define Hn 128
#define Wn 128
#define MAXO 100
#define HWc (Hn*Wn)
#define NBLK (Bn*Hn)   // 2048 blocks, one image row each

struct __align__(16) Obj {
    float x1, y1, x2, y2;        // sorted target box (input coords)
    float cx, cy, wr, hr;        // center (feature coords), radii (as float)
    float i2sx2, i2sy2;          // 1/(2*s^2)
    float inv_gsum;              // 1/max(sum g, 1e-12), 0 if invalid
    float clsf;                  // class as float (pre-clipped)
    int   valid;
    float pad0, pad1, pad2;
};

__device__ Obj    g_obj[Bn][MAXO];
__device__ float4 g_partA[NBLK];   // neg, pos, giou, wsum
__device__ int    g_partN[NBLK];   // npos

// ---------------------------------------------------------------------------
// Kernel 1: per-batch sort + params; gsum parallelized lane-wise
// ---------------------------------------------------------------------------
__global__ void __launch_bounds__(256) prep_kernel(const float* __restrict__ ann) {
    const int b = blockIdx.x;
    const int tid = threadIdx.x;
    __shared__ float s_ann[MAXO * 5];
    __shared__ float s_key[MAXO];
    __shared__ int   s_ord[MAXO];
    __shared__ float t_cx[MAXO], t_cy[MAXO], t_ix2[MAXO], t_iy2[MAXO];
    __shared__ int   t_wr[MAXO], t_hr[MAXO], t_valid[MAXO];

    for (int i = tid; i < MAXO * 5; i += 256) s_ann[i] = ann[(size_t)b * MAXO * 5 + i];
    __syncthreads();

    if (tid < MAXO) {
        float cls  = s_ann[tid * 5 + 4];
        float area = (s_ann[tid * 5 + 3] - s_ann[tid * 5 + 1] + 1.0f)
                   * (s_ann[tid * 5 + 2] - s_ann[tid * 5 + 0] + 1.0f);
        s_key[tid] = (cls >= 0.0f) ? area : -3.4e38f;
    }
    __syncthreads();

    if (tid < MAXO) {   // stable rank sort, descending area
        float ki = s_key[tid];
        int rk = 0;
        #pragma unroll 4
        for (int j = 0; j < MAXO; j++) {
            float kj = s_key[j];
            rk += (kj > ki || (kj == ki && j < tid)) ? 1 : 0;
        }
        s_ord[rk] = tid;
    }
    __syncthreads();

    if (tid < MAXO) {
        int i = s_ord[tid];
        float x1 = s_ann[i*5+0], y1 = s_ann[i*5+1];
        float x2 = s_ann[i*5+2], y2 = s_ann[i*5+3], cls = s_ann[i*5+4];
        int valid = (cls >= 0.0f) ? 1 : 0;

        float cx = truncf((x1 + x2) * 0.5f / 4.0f);
        float cy = truncf((y1 + y2) * 0.5f / 4.0f);
        float fx1 = fminf(fmaxf(x1 * 0.25f, 0.0f), (float)(Wn - 1));
        float fx2 = fminf(fmaxf(x2 * 0.25f, 0.0f), (float)(Wn - 1));
        float fy1 = fminf(fmaxf(y1 * 0.25f, 0.0f), (float)(Hn - 1));
        float fy2 = fminf(fmaxf(y2 * 0.25f, 0.0f), (float)(Hn - 1));
        int hr = (int)((fy2 - fy1) * 0.5f * 0.54f);
        int wr = (int)((fx2 - fx1) * 0.5f * 0.54f);
        float sx = (float)(2 * wr + 1) / 6.0f;
        float sy = (float)(2 * hr + 1) / 6.0f;
        float ix2 = 1.0f / (2.0f * sx * sx);
        float iy2 = 1.0f / (2.0f * sy * sy);

        int ic = (int)cls;
        ic = (ic < 0) ? 0 : ((ic > NC - 1) ? NC - 1 : ic);

        Obj o;
        o.x1 = x1; o.y1 = y1; o.x2 = x2; o.y2 = y2;
        o.cx = cx; o.cy = cy; o.wr = (float)wr; o.hr = (float)hr;
        o.i2sx2 = ix2; o.i2sy2 = iy2;
        o.inv_gsum = 0.0f;              // filled by gsum phase below
        o.clsf = (float)ic;
        o.valid = valid;
        o.pad0 = o.pad1 = o.pad2 = 0.0f;
        g_obj[b][tid] = o;

        t_cx[tid] = cx; t_cy[tid] = cy; t_ix2[tid] = ix2; t_iy2[tid] = iy2;
        t_wr[tid] = wr; t_hr[tid] = hr; t_valid[tid] = valid;
    }
    __syncthreads();

    // gsum: warp w handles objects w, w+8, ... ; lanes split the window sums
    const int w = tid >> 5, lane = tid & 31;
    for (int o = w; o < MAXO; o += 8) {
        if (!t_valid[o]) continue;
        float cx = t_cx[o], cy = t_cy[o];
        int icx = (int)cx, icy = (int)cy;
        int wr = t_wr[o], hr = t_hr[o];
        float ix2 = t_ix2[o], iy2 = t_iy2[o];

        int xa = max(0, icx - wr), xb = min(Wn - 1, icx + wr);
        float sumx = 0.0f;
        for (int xx = xa + lane; xx <= xb; xx += 32) {
            float dx = (float)xx - cx;
            sumx += __expf(-(dx * dx) * ix2);
        }
        int ya = max(0, icy - hr), yb = min(Hn - 1, icy + hr);
        float sumy = 0.0f;
        for (int yy = ya + lane; yy <= yb; yy += 32) {
            float dy = (float)yy - cy;
            sumy += __expf(-(dy * dy) * iy2);
        }
        #pragma unroll
        for (int off = 16; off > 0; off >>= 1) {
            sumx += __shfl_down_sync(0xffffffffu, sumx, off);
            sumy += __shfl_down_sync(0xffffffffu, sumy, off);
        }
        if (lane == 0) {
            float gs = fmaxf(sumx * sumy, 1e-12f);
            g_obj[b][o].inv_gsum = 1.0f / gs;
        }
    }
}

// ---------------------------------------------------------------------------
// Kernel 2: one row per block (grid 2048, block 128, 1 px/thread)
// ---------------------------------------------------------------------------
__global__ void __launch_bounds__(128) main_kernel(const float* __restrict__ hm,
                                                   const float* __restrict__ wh) {
    const int b   = blockIdx.x >> 7;
    const int y   = blockIdx.x & 127;
    const int tid = threadIdx.x;
    const int wpr = tid >> 5, lane = tid & 31;
    const int x   = tid;
    const float fx = (float)x, fy = (float)y;

    __shared__ Obj sh[MAXO];
    {
        const float4* src = (const float4*)&g_obj[b][0];
        float4* dst = (float4*)&sh[0];
        for (int i = tid; i < MAXO * 4; i += 128) dst[i] = src[i];
    }
    __syncthreads();

    // ---- row-filtered list: order-preserving block-wide compaction ----
    __shared__ float fcx[MAXO], fwr[MAXO], fi2[MAXO], fgy[MAXO], fvg[MAXO];
    __shared__ float fb0[MAXO], fb1[MAXO], fb2[MAXO], fb3[MAXO];
    __shared__ int   fcl[MAXO];
    __shared__ int   s_wcnt[4];
    {
        int idx = tid;                     // warp w covers idx w*32..w*32+31
        bool p = false;
        float dy = 0.0f;
        if (idx < MAXO && sh[idx].valid) {
            dy = fy - sh[idx].cy;
            p = fabsf(dy) <= sh[idx].hr;
        }
        unsigned m = __ballot_sync(0xffffffffu, p);
        if (lane == 0) s_wcnt[wpr] = __popc(m);
        __syncthreads();
        int off = 0;
        #pragma unroll
        for (int i = 0; i < 4; i++) off += (i < wpr) ? s_wcnt[i] : 0;
        if (p) {
            int pos = off + __popc(m & ((1u << lane) - 1u));
            fcx[pos] = sh[idx].cx;
            fwr[pos] = sh[idx].wr;
            fi2[pos] = sh[idx].i2sx2;
            fgy[pos] = __expf(-(dy * dy) * sh[idx].i2sy2);
            fvg[pos] = sh[idx].inv_gsum;
            fb0[pos] = sh[idx].x1; fb1[pos] = sh[idx].y1;
            fb2[pos] = sh[idx].x2; fb3[pos] = sh[idx].y2;
            fcl[pos] = (int)sh[idx].clsf;
        }
        __syncthreads();
    }
    const int fcnt = s_wcnt[0] + s_wcnt[1] + s_wcnt[2] + s_wcnt[3];

    float accNeg = 0.0f, accPos = 0.0f, accG = 0.0f, accWs = 0.0f;
    int npos = 0;

    const float* hp = hm + ((size_t)b * NC) * HWc + (size_t)y * Wn + x;

    // ---- sparse: covering scan + focal corrections ----
    int owner = -1;
    float gOwn = 0.0f;
    for (int i = 0; i < fcnt; i++) {
        float dx = fx - fcx[i];
        if (fabsf(dx) <= fwr[i]) {
            float gi = fgy[i] * __expf(-(dx * dx) * fi2[i]);
            owner = i; gOwn = gi;
            bool isMax = true;
            int ci = fcl[i];
            for (int j = 0; j < fcnt; j++) {
                if (j == i || fcl[j] != ci) continue;
                float dxj = fx - fcx[j];
                if (fabsf(dxj) <= fwr[j]) {
                    float gj = fgy[j] * __expf(-(dxj * dxj) * fi2[j]);
                    if (gj > gi || (gj == gi && j < i)) { isMax = false; break; }
                }
            }
            if (isMax) {
                float logit = hp[(size_t)ci * HWc];
                float e   = __expf(logit);
                float u   = 1.0f + e;
                float inv = __fdividef(1.0f, u);   // = 1 - sigmoid
                float s   = e * inv;
                float L   = __logf(u);             // = -log(1 - sigmoid)
                float base = L * s * s;
                if (gi == 1.0f) {
                    accPos += (L - logit) * inv * inv;   // -log(s)*(1-s)^2
                    accNeg -= base;
                    npos++;
                } else {
                    float nt  = 1.0f - gi;
                    float nt2 = nt * nt;
                    accNeg += base * (nt2 * nt2 - 1.0f);
                }
            }
        }
    }

    // ---- GIoU on the owned pixel ----
    if (owner >= 0) {
        float w = gOwn * fvg[owner];
        size_t wb = (size_t)b * 4 * HWc + (size_t)y * Wn + x;
        float wh0 = wh[wb];
        float wh1 = wh[wb + HWc];
        float wh2 = wh[wb + 2 * (size_t)HWc];
        float wh3 = wh[wb + 3 * (size_t)HWc];
        float bx = fx * 4.0f, by = fy * 4.0f;
        float p0 = bx - wh0, p1 = by - wh1, p2 = bx + wh2, p3 = by + wh3;
        float t0 = fb0[owner], t1 = fb1[owner];
        float t2 = fb2[owner], t3 = fb3[owner];
        float ltx = fmaxf(p0, t0), lty = fmaxf(p1, t1);
        float rbx = fminf(p2, t2), rby = fminf(p3, t3);
        float iw = fmaxf(rbx - ltx + 1.0f, 0.0f);
        float ih = fmaxf(rby - lty + 1.0f, 0.0f);
        float ov = iw * ih;
        float ap = (p2 - p0 + 1.0f) * (p3 - p1 + 1.0f);
        float ag = (t2 - t0 + 1.0f) * (t3 - t1 + 1.0f);
        float u  = ap + ag - ov;
        float iou = ov / u;
        float e1x = fminf(p0, t0), e1y = fminf(p1, t1);
        float e2x = fmaxf(p2, t2), e2y = fmaxf(p3, t3);
        float ew = fmaxf(e2x - e1x + 1.0f, 0.0f);
        float eh = fmaxf(e2y - e1y + 1.0f, 0.0f);
        float ea = ew * eh;
        float giou = iou - (ea - u) / ea;
        accG  = (1.0f - giou) * w;
        accWs = w;
    }

    // ---- dense: focal base (tgt = 0) over all 80 classes ----
    {
        float a0 = 0.0f, a1 = 0.0f;
        #pragma unroll 8
        for (int c = 0; c < NC; c += 2) {
            float v0 = hp[(size_t)c * HWc];
            float v1 = hp[(size_t)(c + 1) * HWc];
            float e0 = __expf(v0); float u0 = 1.0f + e0;
            float e1 = __expf(v1); float u1 = 1.0f + e1;
            float s0 = e0 * __fdividef(1.0f, u0);
            float s1 = e1 * __fdividef(1.0f, u1);
            a0 += __logf(u0) * s0 * s0;
            a1 += __logf(u1) * s1 * s1;
        }
        accNeg += a0 + a1;
    }

    // ---- block reduction -> per-block partial ----
    #pragma unroll
    for (int off = 16; off > 0; off >>= 1) {
        accNeg += __shfl_down_sync(0xffffffffu, accNeg, off);
        accPos += __shfl_down_sync(0xffffffffu, accPos, off);
        accG   += __shfl_down_sync(0xffffffffu, accG,   off);
        accWs  += __shfl_down_sync(0xffffffffu, accWs,  off);
        npos   += __shfl_down_sync(0xffffffffu, npos,   off);
    }
    __shared__ float rNeg[4], rPos[4], rG[4], rW[4];
    __shared__ int   rN[4];
    if (lane == 0) { rNeg[wpr] = accNeg; rPos[wpr] = accPos; rG[wpr] = accG; rW[wpr] = accWs; rN[wpr] = npos; }
    __syncthreads();
    if (tid == 0) {
        float sn = 0.f, sp = 0.f, sg = 0.f, sw = 0.f; int np = 0;
        #pragma unroll
        for (int i = 0; i < 4; i++) { sn += rNeg[i]; sp += rPos[i]; sg += rG[i]; sw += rW[i]; np += rN[i]; }
        g_partA[blockIdx.x] = make_float4(sn, sp, sg, sw);
        g_partN[blockIdx.x] = np;
    }
}

// ---------------------------------------------------------------------------
// Kernel 3: reduce 2048 partials (double), write 2 outputs
// ---------------------------------------------------------------------------
__global__ void __launch_bounds__(1024) fin_kernel(float* out, int out_size) {
    int t = threadIdx.x;
    float4 v0 = g_partA[t];
    float4 v1 = g_partA[t + 1024];
    double n = (double)v0.x + (double)v1.x;
    double p = (double)v0.y + (double)v1.y;
    double g = (double)v0.z + (double)v1.z;
    double w = (double)v0.w + (double)v1.w;
    int np = g_partN[t] + g_partN[t + 1024];

    #pragma unroll
    for (int off = 16; off > 0; off >>= 1) {
        n  += __shfl_down_sync(0xffffffffu, n,  off);
        p  += __shfl_down_sync(0xffffffffu, p,  off);
        g  += __shfl_down_sync(0xffffffffu, g,  off);
        w  += __shfl_down_sync(0xffffffffu, w,  off);
        np += __shfl_down_sync(0xffffffffu, np, off);
    }
    __shared__ double sn[32], sp[32], sg[32], sw[32];
    __shared__ int    sN[32];
    int wid = t >> 5, lane = t & 31;
    if (lane == 0) { sn[wid] = n; sp[wid] = p; sg[wid] = g; sw[wid] = w; sN[wid] = np; }
    __syncthreads();
    if (t == 0) {
        double N = 0, P = 0, G = 0, W = 0; int NP = 0;
        #pragma unroll
        for (int i = 0; i < 32; i++) { N += sn[i]; P += sp[i]; G += sg[i]; W += sw[i]; NP += sN[i]; }
        double hm_loss = (NP > 0) ? ((P + N) / (double)NP) : N;   // HM_W = 1
        double wh_loss = G / (W + 1e-4) * 0.1;                    // WH_W = 0.1
        if (out_size >= 1) out[0] = (float)hm_loss;
        if (out_size >= 2) out[1] = (float)wh_loss;
    }
}

// ---------------------------------------------------------------------------
extern "C" void kernel_launch(void* const* d_in, const int* in_sizes, int n_in,
                              void* d_out, int out_size) {
    const float* hm  = (const float*)d_in[0];   // (16, 80, 128, 128)
    const float* wh  = (const float*)d_in[1];   // (16, 4, 128, 128)
    const float* ann = (const float*)d_in[2];   // (16, 100, 5)
    float* out = (float*)d_out;

    prep_kernel<<<Bn, 256>>>(ann);
    main_kernel<<<NBLK, 128>>>(hm, wh);
    fin_kernel<<<1, 1024>>>(out, out_size);
}

// round 7
// speedup vs baseline: 2.5554x; 1.5951x over previous
#include <cuda_runtime.h>
#include <math.h>
#include <stdint.h>

#define Bn 16
#define NC 80
#define Hn 128
#define Wn 128
#define MAXO 100
#define HWc (Hn*Wn)
#define NBLK (Bn*Hn)   // 2048 blocks, one image row each
#define NOBJ (Bn*MAXO) // 1600 objects

struct __align__(16) Obj {
    float x1, y1, x2, y2;        // target box (input coords), original order
    float cx, cy, wr, hr;        // center (feature coords), radii
    float i2sx2, i2sy2;          // 1/(2*s^2)
    float inv_gsum;              // 1/max(sum g, 1e-12), 0 if invalid
    float area;                  // sort key (owner = min area, tie: larger idx)
    int   cls;
    int   valid;
    float pad0, pad1;
};

__device__ Obj    g_obj[Bn][MAXO];
__device__ double g_acc[4];     // neg, pos, giou, wsum
__device__ int    g_npos;
__device__ unsigned g_count;

// ---------------------------------------------------------------------------
// Kernel 1: thread-per-object prep (no sort). Block 0/thread 0 zeroes accs.
// ---------------------------------------------------------------------------
__global__ void __launch_bounds__(128) prep_kernel(const float* __restrict__ ann) {
    int o = blockIdx.x * 128 + threadIdx.x;
    if (blockIdx.x == 0 && threadIdx.x == 0) {
        g_acc[0] = 0.0; g_acc[1] = 0.0; g_acc[2] = 0.0; g_acc[3] = 0.0;
        g_npos = 0; g_count = 0u;
    }
    if (o >= NOBJ) return;
    int b = o / MAXO, i = o - b * MAXO;

    const float* a = ann + (size_t)o * 5;
    float x1 = a[0], y1 = a[1], x2 = a[2], y2 = a[3], cls = a[4];
    int valid = (cls >= 0.0f) ? 1 : 0;

    float area = (y2 - y1 + 1.0f) * (x2 - x1 + 1.0f);
    float cx = truncf((x1 + x2) * 0.5f / 4.0f);
    float cy = truncf((y1 + y2) * 0.5f / 4.0f);
    float fx1 = fminf(fmaxf(x1 * 0.25f, 0.0f), (float)(Wn - 1));
    float fx2 = fminf(fmaxf(x2 * 0.25f, 0.0f), (float)(Wn - 1));
    float fy1 = fminf(fmaxf(y1 * 0.25f, 0.0f), (float)(Hn - 1));
    float fy2 = fminf(fmaxf(y2 * 0.25f, 0.0f), (float)(Hn - 1));
    int hr = (int)((fy2 - fy1) * 0.5f * 0.54f);
    int wr = (int)((fx2 - fx1) * 0.5f * 0.54f);
    float sx = (float)(2 * wr + 1) / 6.0f;
    float sy = (float)(2 * hr + 1) / 6.0f;
    float ix2 = 1.0f / (2.0f * sx * sx);
    float iy2 = 1.0f / (2.0f * sy * sy);

    // analytic gsum: separable clipped-window sums (windows <= ~15 wide)
    int icx = (int)cx, icy = (int)cy;
    float sumx = 0.0f;
    int xa = max(0, icx - wr), xb = min(Wn - 1, icx + wr);
    for (int xx = xa; xx <= xb; xx++) {
        float dx = (float)xx - cx;
        sumx += __expf(-(dx * dx) * ix2);
    }
    float sumy = 0.0f;
    int ya = max(0, icy - hr), yb = min(Hn - 1, icy + hr);
    for (int yy = ya; yy <= yb; yy++) {
        float dy = (float)yy - cy;
        sumy += __expf(-(dy * dy) * iy2);
    }
    float gs = fmaxf(sumx * sumy, 1e-12f);

    int ic = (int)cls;
    ic = (ic < 0) ? 0 : ((ic > NC - 1) ? NC - 1 : ic);

    Obj ob;
    ob.x1 = x1; ob.y1 = y1; ob.x2 = x2; ob.y2 = y2;
    ob.cx = cx; ob.cy = cy; ob.wr = (float)wr; ob.hr = (float)hr;
    ob.i2sx2 = ix2; ob.i2sy2 = iy2;
    ob.inv_gsum = valid ? (1.0f / gs) : 0.0f;
    ob.area = area;
    ob.cls = ic; ob.valid = valid;
    ob.pad0 = ob.pad1 = 0.0f;
    g_obj[b][i] = ob;
}

// ---------------------------------------------------------------------------
// Kernel 2: one row per block; last block finalizes (no third kernel)
// ---------------------------------------------------------------------------
__global__ void __launch_bounds__(128) main_kernel(const float* __restrict__ hm,
                                                   const float* __restrict__ wh,
                                                   float* out, int out_size) {
    const int b   = blockIdx.x >> 7;
    const int y   = blockIdx.x & 127;
    const int tid = threadIdx.x;
    const int wpr = tid >> 5, lane = tid & 31;
    const int x   = tid;
    const float fx = (float)x, fy = (float)y;

    // ---- row-filtered list: order-preserving block-wide compaction ----
    __shared__ float fcx[MAXO], fwr[MAXO], fi2[MAXO], fgy[MAXO], fvg[MAXO];
    __shared__ float fb0[MAXO], fb1[MAXO], fb2[MAXO], fb3[MAXO], far_[MAXO];
    __shared__ int   fcl[MAXO];
    __shared__ int   s_wcnt[4];
    {
        const Obj* ob = &g_obj[b][0];
        int idx = tid;
        bool p = false;
        float dy = 0.0f;
        if (idx < MAXO) {
            const Obj& o = ob[idx];
            if (o.valid) {
                dy = fy - o.cy;
                p = fabsf(dy) <= o.hr;
            }
        }
        unsigned m = __ballot_sync(0xffffffffu, p);
        if (lane == 0) s_wcnt[wpr] = __popc(m);
        __syncthreads();
        int off = 0;
        #pragma unroll
        for (int i = 0; i < 4; i++) off += (i < wpr) ? s_wcnt[i] : 0;
        if (p) {
            const Obj& o = ob[idx];
            int pos = off + __popc(m & ((1u << lane) - 1u));
            fcx[pos] = o.cx;
            fwr[pos] = o.wr;
            fi2[pos] = o.i2sx2;
            fgy[pos] = __expf(-(dy * dy) * o.i2sy2);
            fvg[pos] = o.inv_gsum;
            fb0[pos] = o.x1; fb1[pos] = o.y1;
            fb2[pos] = o.x2; fb3[pos] = o.y2;
            far_[pos] = o.area;
            fcl[pos] = o.cls;
        }
        __syncthreads();
    }
    const int fcnt = s_wcnt[0] + s_wcnt[1] + s_wcnt[2] + s_wcnt[3];

    float accNeg = 0.0f, accPos = 0.0f, accG = 0.0f, accWs = 0.0f;
    int npos = 0;

    const float* hp = hm + ((size_t)b * NC) * HWc + (size_t)y * Wn + x;

    // ---- sparse: covering scan; owner = min area (tie: later index) ----
    int owner = -1;
    float gOwn = 0.0f, bestA = 3.4e38f;
    for (int i = 0; i < fcnt; i++) {
        float dx = fx - fcx[i];
        if (fabsf(dx) <= fwr[i]) {
            float gi = fgy[i] * __expf(-(dx * dx) * fi2[i]);
            if (far_[i] <= bestA) { bestA = far_[i]; owner = i; gOwn = gi; }
            bool isMax = true;
            int ci = fcl[i];
            for (int j = 0; j < fcnt; j++) {
                if (j == i || fcl[j] != ci) continue;
                float dxj = fx - fcx[j];
                if (fabsf(dxj) <= fwr[j]) {
                    float gj = fgy[j] * __expf(-(dxj * dxj) * fi2[j]);
                    if (gj > gi || (gj == gi && j < i)) { isMax = false; break; }
                }
            }
            if (isMax) {
                float logit = hp[(size_t)ci * HWc];
                float e   = __expf(logit);
                float u   = 1.0f + e;
                float inv = __fdividef(1.0f, u);   // = 1 - sigmoid
                float s   = e * inv;
                float L   = __logf(u);             // = -log(1 - sigmoid)
                float base = L * s * s;
                if (gi == 1.0f) {
                    accPos += (L - logit) * inv * inv;   // -log(s)*(1-s)^2
                    accNeg -= base;
                    npos++;
                } else {
                    float nt  = 1.0f - gi;
                    float nt2 = nt * nt;
                    accNeg += base * (nt2 * nt2 - 1.0f);
                }
            }
        }
    }

    // ---- GIoU on the owned pixel ----
    if (owner >= 0) {
        float w = gOwn * fvg[owner];
        size_t wb = (size_t)b * 4 * HWc + (size_t)y * Wn + x;
        float wh0 = wh[wb];
        float wh1 = wh[wb + HWc];
        float wh2 = wh[wb + 2 * (size_t)HWc];
        float wh3 = wh[wb + 3 * (size_t)HWc];
        float bx = fx * 4.0f, by = fy * 4.0f;
        float p0 = bx - wh0, p1 = by - wh1, p2 = bx + wh2, p3 = by + wh3;
        float t0 = fb0[owner], t1 = fb1[owner];
        float t2 = fb2[owner], t3 = fb3[owner];
        float ltx = fmaxf(p0, t0), lty = fmaxf(p1, t1);
        float rbx = fminf(p2, t2), rby = fminf(p3, t3);
        float iw = fmaxf(rbx - ltx + 1.0f, 0.0f);
        float ih = fmaxf(rby - lty + 1.0f, 0.0f);
        float ov = iw * ih;
        float ap = (p2 - p0 + 1.0f) * (p3 - p1 + 1.0f);
        float ag = (t2 - t0 + 1.0f) * (t3 - t1 + 1.0f);
        float u  = ap + ag - ov;
        float iou = ov / u;
        float e1x = fminf(p0, t0), e1y = fminf(p1, t1);
        float e2x = fmaxf(p2, t2), e2y = fmaxf(p3, t3);
        float ew = fmaxf(e2x - e1x + 1.0f, 0.0f);
        float eh = fmaxf(e2y - e1y + 1.0f, 0.0f);
        float ea = ew * eh;
        float giou = iou - (ea - u) / ea;
        accG  = (1.0f - giou) * w;
        accWs = w;
    }

    // ---- dense: focal base (tgt = 0) over all 80 classes ----
    {
        float a0 = 0.0f, a1 = 0.0f;
        #pragma unroll 8
        for (int c = 0; c < NC; c += 2) {
            float v0 = hp[(size_t)c * HWc];
            float v1 = hp[(size_t)(c + 1) * HWc];
            float e0 = __expf(v0); float u0 = 1.0f + e0;
            float e1 = __expf(v1); float u1 = 1.0f + e1;
            float s0 = e0 * __fdividef(1.0f, u0);
            float s1 = e1 * __fdividef(1.0f, u1);
            a0 += __logf(u0) * s0 * s0;
            a1 += __logf(u1) * s1 * s1;
        }
        accNeg += a0 + a1;
    }

    // ---- block reduction -> global double REDs ----
    #pragma unroll
    for (int off = 16; off > 0; off >>= 1) {
        accNeg += __shfl_down_sync(0xffffffffu, accNeg, off);
        accPos += __shfl_down_sync(0xffffffffu, accPos, off);
        accG   += __shfl_down_sync(0xffffffffu, accG,   off);
        accWs  += __shfl_down_sync(0xffffffffu, accWs,  off);
        npos   += __shfl_down_sync(0xffffffffu, npos,   off);
    }
    __shared__ float rNeg[4], rPos[4], rG[4], rW[4];
    __shared__ int   rN[4];
    if (lane == 0) { rNeg[wpr] = accNeg; rPos[wpr] = accPos; rG[wpr] = accG; rW[wpr] = accWs; rN[wpr] = npos; }
    __syncthreads();
    if (tid == 0) {
        float sn = 0.f, sp = 0.f, sg = 0.f, sw = 0.f; int np = 0;
        #pragma unroll
        for (int i = 0; i < 4; i++) { sn += rNeg[i]; sp += rPos[i]; sg += rG[i]; sw += rW[i]; np += rN[i]; }
        atomicAdd(&g_acc[0], (double)sn);
        atomicAdd(&g_acc[1], (double)sp);
        atomicAdd(&g_acc[2], (double)sg);
        atomicAdd(&g_acc[3], (double)sw);
        if (np) atomicAdd(&g_npos, np);
    }

    // ---- last block finalizes, writes output, resets for next replay ----
    __shared__ int s_last;
    if (tid == 0) {
        __threadfence();
        unsigned old = atomicAdd(&g_count, 1u);
        s_last = (old == NBLK - 1) ? 1 : 0;
    }
    __syncthreads();
    if (s_last && tid == 0) {
        double neg = atomicAdd(&g_acc[0], 0.0);
        double pos = atomicAdd(&g_acc[1], 0.0);
        double gi  = atomicAdd(&g_acc[2], 0.0);
        double ws  = atomicAdd(&g_acc[3], 0.0);
        int np = atomicAdd(&g_npos, 0);
        double hm_loss = (np > 0) ? ((pos + neg) / (double)np) : neg;  // HM_W = 1
        double wh_loss = gi / (ws + 1e-4) * 0.1;                        // WH_W = 0.1
        if (out_size >= 1) out[0] = (float)hm_loss;
        if (out_size >= 2) out[1] = (float)wh_loss;
        // reset for next graph replay
        g_acc[0] = 0.0; g_acc[1] = 0.0; g_acc[2] = 0.0; g_acc[3] = 0.0;
        g_npos = 0; g_count = 0u;
        __threadfence();
    }
}

// ---------------------------------------------------------------------------
extern "C" void kernel_launch(void* const* d_in, const int* in_sizes, int n_in,
                              void* d_out, int out_size) {
    const float* hm  = (const float*)d_in[0];   // (16, 80, 128, 128)
    const float* wh  = (const float*)d_in[1];   // (16, 4, 128, 128)
    const float* ann = (const float*)d_in[2];   // (16, 100, 5)
    float* out = (float*)d_out;

    prep_kernel<<<(NOBJ + 127) / 128, 128>>>(ann);
    main_kernel<<<NBLK, 128>>>(hm, wh, out, out_size);
}